// round 14
// baseline (speedup 1.0000x reference)
#include <cuda_runtime.h>
#include <cuda_fp16.h>
#include <cstdint>
#include <math.h>

#define N_NODE   20000
#define N_EDGE   200000
#define EMBED    256
#define PAIR_DIM 128
#define HEADS    16
#define LN_EPS   1e-5f
#define SCALING  0.25f            // folded into Wq rows of Wall

// ---------------- scratch (device globals; no allocation) ----------------
__device__ uint4 g_qnh4 [N_NODE * 32];        // qn fp16 (256/row)
__device__ uint4 g_Wallh4[768 * 32];          // Wall fp16: Wq*S, Wk, Wvf, pad
__device__ uint4 g_qh4[N_NODE * 32];          // q fp16
__device__ uint4 g_kh4[N_NODE * 32];          // k fp16
__device__ uint4 g_vwh4[N_NODE * 6];          // vw fp16 [n][d*16+h] (96B/row)
__device__ float g_ex[N_EDGE * HEADS];
__device__ float g_denom[N_NODE * HEADS];     // after recip: 1/denom
__device__ float g_bias[N_EDGE * HEADS];      // FINAL per-head logit bias
__device__ uint4 g_Wbp4[16 * 16];             // Wb' fp16 [16 x 128]
__device__ float g_t1[HEADS];
__device__ float g_t2p[HEADS];                // t2 + bb

__device__ __forceinline__ unsigned smem_u32(const void* p) {
    unsigned a;
    asm("{ .reg .u64 t; cvta.to.shared.u64 t, %1; cvt.u32.u64 %0, t; }" : "=r"(a) : "l"(p));
    return a;
}

// ---------------- 1. fused prep (one launch; NO pair pass) ----------------
#define PB_WALL 768
#define PB_LN   2500
#define PB_INIT 1250
#define PB_WBP  8
#define PB_T    2
#define PREP_BLKS (PB_WALL + PB_LN + PB_INIT + PB_WBP + PB_T)
__global__ __launch_bounds__(256) void prep(
        const float* __restrict__ query,
        const float* __restrict__ ln_w, const float* __restrict__ ln_b,
        const float* __restrict__ Wq, const float* __restrict__ Wk,
        const float* __restrict__ Wv,
        const float* __restrict__ Wf1, const float* __restrict__ Wf2,
        const float* __restrict__ Wf3,
        float* __restrict__ out,
        const float* __restrict__ bf1, const float* __restrict__ bf2,
        const float* __restrict__ bf3,
        const float* __restrict__ pln_w, const float* __restrict__ pln_b,
        const float* __restrict__ Wb, const float* __restrict__ bb) {
    int blk = blockIdx.x;
    if (blk < PB_WALL) {
        int idx = blk * 256 + threadIdx.x;
        int row = idx >> 8;
        int c   = idx & 255;
        float val = 0.f;
        if (row < 256) {
            val = Wq[row * EMBED + c] * SCALING;
        } else if (row < 512) {
            val = Wk[(row - 256) * EMBED + c];
        } else if (row < 560) {
            int r = row - 512;
            int d = r >> 4, h = r & 15;
            const float* Wf = (d == 0) ? Wf1 : (d == 1) ? Wf2 : Wf3;
            float s = 0.f;
            #pragma unroll
            for (int hd = 0; hd < 16; hd++)
                s += Wf[h * 16 + hd] * Wv[(h * 16 + hd) * EMBED + c];
            val = s;
        }
        ((__half*)g_Wallh4)[idx] = __float2half_rn(val);
        return;
    }
    blk -= PB_WALL;
    if (blk < PB_LN) {
        int node = blk * 8 + (threadIdx.x >> 5);
        int lane = threadIdx.x & 31;
        if (node >= N_NODE) return;
        const float4* x = (const float4*)(query + (size_t)node * EMBED);
        float4 v[2];
        float s = 0.f, sq = 0.f;
        #pragma unroll
        for (int i = 0; i < 2; i++) {
            v[i] = x[lane + 32 * i];
            s  += v[i].x + v[i].y + v[i].z + v[i].w;
            sq += v[i].x*v[i].x + v[i].y*v[i].y + v[i].z*v[i].z + v[i].w*v[i].w;
        }
        #pragma unroll
        for (int o = 16; o > 0; o >>= 1) {
            s  += __shfl_xor_sync(0xffffffffu, s,  o);
            sq += __shfl_xor_sync(0xffffffffu, sq, o);
        }
        float mean = s * (1.f / EMBED);
        float var  = sq * (1.f / EMBED) - mean * mean;
        float rstd = rsqrtf(var + LN_EPS);
        uint2* o = (uint2*)g_qnh4 + (size_t)node * 64;
        #pragma unroll
        for (int i = 0; i < 2; i++) {
            int j = lane + 32 * i;
            float4 w = ((const float4*)ln_w)[j];
            float4 b = ((const float4*)ln_b)[j];
            float rx = (v[i].x - mean) * rstd * w.x + b.x;
            float ry = (v[i].y - mean) * rstd * w.y + b.y;
            float rz = (v[i].z - mean) * rstd * w.z + b.z;
            float rw = (v[i].w - mean) * rstd * w.w + b.w;
            uint2 pk;
            __half2 p0 = __floats2half2_rn(rx, ry);
            __half2 p1 = __floats2half2_rn(rz, rw);
            pk.x = *(unsigned*)&p0;
            pk.y = *(unsigned*)&p1;
            o[j] = pk;
        }
        return;
    }
    blk -= PB_LN;
    if (blk < PB_INIT) {
        int i = blk * 256 + threadIdx.x;
        if (i < N_NODE * HEADS) g_denom[i] = 0.f;
        if (i < N_NODE * 3) {
            int d = i % 3;
            out[i] = (d == 0) ? bf1[0] : (d == 1) ? bf2[0] : bf3[0];
        }
        return;
    }
    blk -= PB_INIT;
    if (blk < PB_WBP) {
        int idx = blk * 256 + threadIdx.x;       // 0..2047
        int h = idx >> 7, c = idx & 127;
        ((__half*)g_Wbp4)[idx] = __float2half_rn(pln_w[c] * Wb[h * PAIR_DIM + c]);
        return;
    }
    blk -= PB_WBP;
    {
        int h = blk * 8 + (threadIdx.x >> 5);
        int lane = threadIdx.x & 31;
        if (h >= HEADS) return;
        float t1 = 0.f, t2 = 0.f;
        #pragma unroll
        for (int i = 0; i < 4; i++) {
            int c = lane + 32 * i;
            float wb = Wb[h * PAIR_DIM + c];
            t1 += pln_w[c] * wb;
            t2 += pln_b[c] * wb;
        }
        #pragma unroll
        for (int o = 16; o > 0; o >>= 1) {
            t1 += __shfl_xor_sync(0xffffffffu, t1, o);
            t2 += __shfl_xor_sync(0xffffffffu, t2, o);
        }
        if (lane == 0) {
            g_t1[h]  = t1;
            g_t2p[h] = t2 + bb[h];
        }
    }
}

// ---------------- 2. HMMA GEMM: C[20000 x 640] = qn . Wall^T ----------------
#define APAD 72
__global__ __launch_bounds__(256) void gemm_mma() {
    __shared__ __half As[128][APAD];
    __shared__ __half Bs[128][APAD];
    int tid  = threadIdx.x;
    int wid  = tid >> 5;
    int lane = tid & 31;
    int wm = wid >> 1;
    int wn = wid & 1;
    int m0  = blockIdx.y * 128;
    int n0g = blockIdx.x * 128;

    float acc[2][8][4];
    #pragma unroll
    for (int i = 0; i < 2; i++)
        #pragma unroll
        for (int j = 0; j < 8; j++)
            #pragma unroll
            for (int t = 0; t < 4; t++) acc[i][j][t] = 0.f;

    const int fr = tid >> 3;
    const int fu = tid & 7;

    for (int k0 = 0; k0 < EMBED; k0 += 64) {
        #pragma unroll
        for (int i = 0; i < 4; i++) {
            int row = fr + 32 * i;
            int m = m0 + row;
            uint4 av = make_uint4(0, 0, 0, 0);
            if (m < N_NODE) av = g_qnh4[(size_t)m * 32 + (k0 >> 3) + fu];
            *(uint4*)&As[row][fu * 8] = av;
            uint4 bv = g_Wallh4[(size_t)(n0g + row) * 32 + (k0 >> 3) + fu];
            *(uint4*)&Bs[row][fu * 8] = bv;
        }
        __syncthreads();

        #pragma unroll
        for (int kk = 0; kk < 4; kk++) {
            int kc = kk * 16;
            unsigned a[2][4];
            #pragma unroll
            for (int mt = 0; mt < 2; mt++) {
                int row = wm * 32 + mt * 16 + (lane & 15);
                int col = kc + ((lane >> 4) << 3);
                unsigned addr = smem_u32(&As[row][col]);
                asm volatile("ldmatrix.sync.aligned.m8n8.x4.shared.b16 {%0,%1,%2,%3}, [%4];"
                             : "=r"(a[mt][0]), "=r"(a[mt][1]), "=r"(a[mt][2]), "=r"(a[mt][3])
                             : "r"(addr));
            }
            unsigned b[8][2];
            #pragma unroll
            for (int p = 0; p < 4; p++) {
                int row = wn * 64 + p * 16 + ((lane >> 4) << 3) + (lane & 7);
                int col = kc + (((lane >> 3) & 1) << 3);
                unsigned addr = smem_u32(&Bs[row][col]);
                asm volatile("ldmatrix.sync.aligned.m8n8.x4.shared.b16 {%0,%1,%2,%3}, [%4];"
                             : "=r"(b[2*p][0]), "=r"(b[2*p][1]), "=r"(b[2*p+1][0]), "=r"(b[2*p+1][1])
                             : "r"(addr));
            }
            #pragma unroll
            for (int mt = 0; mt < 2; mt++)
                #pragma unroll
                for (int nt = 0; nt < 8; nt++)
                    asm volatile("mma.sync.aligned.m16n8k16.row.col.f32.f16.f16.f32 "
                                 "{%0,%1,%2,%3}, {%4,%5,%6,%7}, {%8,%9}, {%0,%1,%2,%3};"
                                 : "+f"(acc[mt][nt][0]), "+f"(acc[mt][nt][1]),
                                   "+f"(acc[mt][nt][2]), "+f"(acc[mt][nt][3])
                                 : "r"(a[mt][0]), "r"(a[mt][1]), "r"(a[mt][2]), "r"(a[mt][3]),
                                   "r"(b[nt][0]), "r"(b[nt][1]));
        }
        __syncthreads();
    }

    int gr = lane >> 2, gc = lane & 3;
    __half* qh = (__half*)g_qh4;
    __half* kh = (__half*)g_kh4;
    __half* vwh = (__half*)g_vwh4;
    #pragma unroll
    for (int mt = 0; mt < 2; mt++) {
        #pragma unroll
        for (int hf = 0; hf < 2; hf++) {
            int m = m0 + wm * 32 + mt * 16 + gr + hf * 8;
            if (m >= N_NODE) continue;
            #pragma unroll
            for (int nt = 0; nt < 8; nt++) {
                float c0 = acc[mt][nt][hf * 2 + 0];
                float c1 = acc[mt][nt][hf * 2 + 1];
                int colg = n0g + wn * 64 + nt * 8 + gc * 2;
                if (colg < 256) {
                    __half2 h = __floats2half2_rn(c0, c1);
                    *(__half2*)&qh[(size_t)m * 256 + colg] = h;
                } else if (colg < 512) {
                    __half2 h = __floats2half2_rn(c0, c1);
                    *(__half2*)&kh[(size_t)m * 256 + (colg - 256)] = h;
                } else if (colg < 560) {
                    __half2 h = __floats2half2_rn(c0, c1);
                    *(__half2*)&vwh[(size_t)m * 48 + (colg - 512)] = h;
                }
            }
        }
    }
}

// ---------------- 3. bias GEMM: fp32 pair in, half-warp-row fill, LN-folded --
__global__ __launch_bounds__(128) void bias_gemm(const float* __restrict__ pair) {
    __shared__ __half As[128][136];
    __shared__ __half Bs[16][136];
    __shared__ float2 sStat[128];          // (rstd, mean*rstd)
    int tid  = threadIdx.x;
    int wid  = tid >> 5;
    int lane = tid & 31;
    int m0 = blockIdx.x * 128;

    int half = lane >> 4;      // 0/1: row within pair
    int hl   = lane & 15;      // position in half-warp
    #pragma unroll
    for (int i = 0; i < 16; i++) {
        int row = wid * 2 + 8 * i + half;       // tiles all 128 rows uniquely
        int e = m0 + row;
        float4 pa = make_float4(0.f, 0.f, 0.f, 0.f);
        float4 pb = pa;
        if (e < N_EDGE) {
            const float4* pr = (const float4*)(pair + (size_t)e * PAIR_DIM);
            pa = pr[hl * 2];
            pb = pr[hl * 2 + 1];
        }
        float s  = pa.x + pa.y + pa.z + pa.w + pb.x + pb.y + pb.z + pb.w;
        float sq = pa.x*pa.x + pa.y*pa.y + pa.z*pa.z + pa.w*pa.w
                 + pb.x*pb.x + pb.y*pb.y + pb.z*pb.z + pb.w*pb.w;
        #pragma unroll
        for (int o = 1; o < 16; o <<= 1) {       // segmented within half-warp
            s  += __shfl_xor_sync(0xffffffffu, s,  o);
            sq += __shfl_xor_sync(0xffffffffu, sq, o);
        }
        if (hl == 0) {
            float mean = s * (1.f / PAIR_DIM);
            float var  = sq * (1.f / PAIR_DIM) - mean * mean;
            float rstd = rsqrtf(var + LN_EPS);
            sStat[row] = make_float2(rstd, mean * rstd);
        }
        uint4 pk;
        __half2 h0 = __floats2half2_rn(pa.x, pa.y);
        __half2 h1 = __floats2half2_rn(pa.z, pa.w);
        __half2 h2 = __floats2half2_rn(pb.x, pb.y);
        __half2 h3 = __floats2half2_rn(pb.z, pb.w);
        pk.x = *(unsigned*)&h0;
        pk.y = *(unsigned*)&h1;
        pk.z = *(unsigned*)&h2;
        pk.w = *(unsigned*)&h3;
        *(uint4*)&As[row][hl * 8] = pk;
    }
    // fill B: 16 rows x 16 uint4
    #pragma unroll
    for (int i = 0; i < 2; i++) {
        int v = tid + 128 * i;
        int row = v >> 4, u = v & 15;
        *(uint4*)&Bs[row][u * 8] = g_Wbp4[row * 16 + u];
    }
    __syncthreads();

    float acc[2][2][4];
    #pragma unroll
    for (int i = 0; i < 2; i++)
        #pragma unroll
        for (int j = 0; j < 2; j++)
            #pragma unroll
            for (int t = 0; t < 4; t++) acc[i][j][t] = 0.f;

    #pragma unroll
    for (int kk = 0; kk < 8; kk++) {
        int kc = kk * 16;
        unsigned a[2][4];
        #pragma unroll
        for (int mt = 0; mt < 2; mt++) {
            int row = wid * 32 + mt * 16 + (lane & 15);
            int col = kc + ((lane >> 4) << 3);
            unsigned addr = smem_u32(&As[row][col]);
            asm volatile("ldmatrix.sync.aligned.m8n8.x4.shared.b16 {%0,%1,%2,%3}, [%4];"
                         : "=r"(a[mt][0]), "=r"(a[mt][1]), "=r"(a[mt][2]), "=r"(a[mt][3])
                         : "r"(addr));
        }
        unsigned b[2][2];
        {
            int row = ((lane >> 4) << 3) + (lane & 7);
            int col = kc + (((lane >> 3) & 1) << 3);
            unsigned addr = smem_u32(&Bs[row][col]);
            asm volatile("ldmatrix.sync.aligned.m8n8.x4.shared.b16 {%0,%1,%2,%3}, [%4];"
                         : "=r"(b[0][0]), "=r"(b[0][1]), "=r"(b[1][0]), "=r"(b[1][1])
                         : "r"(addr));
        }
        #pragma unroll
        for (int mt = 0; mt < 2; mt++)
            #pragma unroll
            for (int nt = 0; nt < 2; nt++)
                asm volatile("mma.sync.aligned.m16n8k16.row.col.f32.f16.f16.f32 "
                             "{%0,%1,%2,%3}, {%4,%5,%6,%7}, {%8,%9}, {%0,%1,%2,%3};"
                             : "+f"(acc[mt][nt][0]), "+f"(acc[mt][nt][1]),
                               "+f"(acc[mt][nt][2]), "+f"(acc[mt][nt][3])
                             : "r"(a[mt][0]), "r"(a[mt][1]), "r"(a[mt][2]), "r"(a[mt][3]),
                               "r"(b[nt][0]), "r"(b[nt][1]));
    }

    // epilogue: finalize bias = rstd*dot - mean*rstd*t1[h] + t2p[h]
    int gr = lane >> 2, gc = lane & 3;
    float t1v[4], t2v[4];
    #pragma unroll
    for (int nt = 0; nt < 2; nt++) {
        t1v[nt*2+0] = g_t1[nt*8 + gc*2 + 0];
        t1v[nt*2+1] = g_t1[nt*8 + gc*2 + 1];
        t2v[nt*2+0] = g_t2p[nt*8 + gc*2 + 0];
        t2v[nt*2+1] = g_t2p[nt*8 + gc*2 + 1];
    }
    #pragma unroll
    for (int mt = 0; mt < 2; mt++) {
        #pragma unroll
        for (int hf = 0; hf < 2; hf++) {
            int row = wid * 32 + mt * 16 + gr + hf * 8;
            int e = m0 + row;
            if (e >= N_EDGE) continue;
            float2 st = sStat[row];
            #pragma unroll
            for (int nt = 0; nt < 2; nt++) {
                float d0 = acc[mt][nt][hf * 2 + 0];
                float d1 = acc[mt][nt][hf * 2 + 1];
                float2 f2;
                f2.x = fmaf(st.x, d0, fmaf(-st.y, t1v[nt*2+0], t2v[nt*2+0]));
                f2.y = fmaf(st.x, d1, fmaf(-st.y, t1v[nt*2+1], t2v[nt*2+1]));
                *(float2*)&g_bias[(size_t)e * 16 + nt * 8 + gc * 2] = f2;
            }
        }
    }
}

// ---------------- 4. qk + exp + denom (4 edges per warp -> MLP 8) -----------
__global__ __launch_bounds__(256) void qk_exp(const int* __restrict__ ei) {
    int w = (blockIdx.x * blockDim.x + threadIdx.x) >> 5;   // warp id
    int lane = threadIdx.x & 31;
    int eBase = 4 * w;
    if (eBase >= N_EDGE) return;

    int src[4], dst[4];
    #pragma unroll
    for (int t = 0; t < 4; t++) {
        src[t] = ei[2 * (eBase + t) + 0];
        dst[t] = ei[2 * (eBase + t) + 1];
    }

    // 8 independent gathers issued back-to-back (MLP=8)
    uint4 qv[4], kv[4];
    #pragma unroll
    for (int t = 0; t < 4; t++) {
        qv[t] = g_qh4[(size_t)src[t] * 32 + lane];
        kv[t] = g_kh4[(size_t)dst[t] * 32 + lane];
    }

    float qk[4];
    #pragma unroll
    for (int t = 0; t < 4; t++) {
        const __half2* qh = (const __half2*)&qv[t];
        const __half2* kh = (const __half2*)&kv[t];
        float s = 0.f;
        #pragma unroll
        for (int j = 0; j < 4; j++) {
            float2 a = __half22float2(qh[j]);
            float2 b = __half22float2(kh[j]);
            s += a.x * b.x + a.y * b.y;
        }
        qk[t] = s;
    }
    #pragma unroll
    for (int t = 0; t < 4; t++)
        qk[t] += __shfl_xor_sync(0xffffffffu, qk[t], 1);   // head h = lane>>1

    int h = lane >> 1;
    if (!(lane & 1)) {
        #pragma unroll
        for (int t = 0; t < 4; t++) {
            int e = eBase + t;
            float ex = __expf(qk[t] + g_bias[(size_t)e * 16 + h]);
            g_ex[(size_t)e * HEADS + h] = ex;
            atomicAdd(&g_denom[src[t] * HEADS + h], ex);
        }
    }
}

// ---------------- 5. reciprocal of denom (in place) ----------------
__global__ void recip_denom() {
    int i = blockIdx.x * blockDim.x + threadIdx.x;
    if (i >= (N_NODE * HEADS) / 4) return;
    float4 d = ((const float4*)g_denom)[i];
    float4 r;
    r.x = __frcp_rn(d.x);
    r.y = __frcp_rn(d.y);
    r.z = __frcp_rn(d.z);
    r.w = __frcp_rn(d.w);
    ((float4*)g_denom)[i] = r;
}

// ---------------- 6. scatter output (thread per edge, fp16 vw) ----------------
__global__ void scatter_out(const int* __restrict__ ei, const float* __restrict__ edge_diff,
                            float* __restrict__ out) {
    int e = blockIdx.x * blockDim.x + threadIdx.x;
    if (e >= N_EDGE) return;
    int src = ei[2 * e];
    int dst = ei[2 * e + 1];

    const float4* exv = (const float4*)(g_ex + (size_t)e * HEADS);
    const float4* dnv = (const float4*)(g_denom + src * HEADS);   // reciprocals
    float prob[16];
    #pragma unroll
    for (int i = 0; i < 4; i++) {
        float4 ex4 = exv[i];
        float4 rd4 = dnv[i];
        prob[4*i+0] = ex4.x * rd4.x;
        prob[4*i+1] = ex4.y * rd4.y;
        prob[4*i+2] = ex4.z * rd4.z;
        prob[4*i+3] = ex4.w * rd4.w;
    }
    // vw fp16: 6 uint4 per node row; [d*16+h], 8 halves per uint4
    const uint4* vw4 = &g_vwh4[(size_t)dst * 6];
    uint4 v[6];
    #pragma unroll
    for (int i = 0; i < 6; i++) v[i] = vw4[i];
    float s[3] = {0.f, 0.f, 0.f};
    #pragma unroll
    for (int d = 0; d < 3; d++) {
        const __half2* hp = (const __half2*)&v[d * 2];
        #pragma unroll
        for (int j = 0; j < 8; j++) {
            float2 f = __half22float2(hp[j]);
            s[d] += prob[2*j] * f.x + prob[2*j+1] * f.y;
        }
    }
    const float* ed = edge_diff + (size_t)e * 3;
    atomicAdd(&out[src * 3 + 0], ed[0] * s[0]);
    atomicAdd(&out[src * 3 + 1], ed[1] * s[1]);
    atomicAdd(&out[src * 3 + 2], ed[2] * s[2]);
}

// ---------------- launch ----------------
extern "C" void kernel_launch(void* const* d_in, const int* in_sizes, int n_in,
                              void* d_out, int out_size) {
    const float* query      = (const float*)d_in[0];
    const int*   edge_index = (const int*)  d_in[1];
    const float* edge_diff  = (const float*)d_in[2];
    const float* pair       = (const float*)d_in[3];
    const float* ln_w       = (const float*)d_in[4];
    const float* ln_b       = (const float*)d_in[5];
    const float* pln_w      = (const float*)d_in[6];
    const float* pln_b      = (const float*)d_in[7];
    const float* Wq         = (const float*)d_in[8];
    const float* Wk         = (const float*)d_in[9];
    const float* Wv         = (const float*)d_in[10];
    const float* Wb         = (const float*)d_in[11];
    const float* bb         = (const float*)d_in[12];
    const float* Wf1        = (const float*)d_in[13];
    const float* bf1        = (const float*)d_in[14];
    const float* Wf2        = (const float*)d_in[15];
    const float* bf2        = (const float*)d_in[16];
    const float* Wf3        = (const float*)d_in[17];
    const float* bf3        = (const float*)d_in[18];
    float* out = (float*)d_out;

    prep<<<PREP_BLKS, 256>>>(query, ln_w, ln_b, Wq, Wk, Wv, Wf1, Wf2, Wf3,
                             out, bf1, bf2, bf3, pln_w, pln_b, Wb, bb);
    bias_gemm<<<(N_EDGE + 127) / 128, 128>>>(pair);
    gemm_mma<<<dim3(5, (N_NODE + 127) / 128), 256>>>();
    qk_exp<<<(N_EDGE / 4 * 32 + 255) / 256, 256>>>(edge_index);
    recip_denom<<<(N_NODE * HEADS / 4 + 255) / 256, 256>>>();
    scatter_out<<<(N_EDGE + 255) / 256, 256>>>(edge_index, edge_diff, out);
}

// round 15
// speedup vs baseline: 1.0365x; 1.0365x over previous
#include <cuda_runtime.h>
#include <cuda_fp16.h>
#include <cstdint>
#include <math.h>

#define N_NODE   20000
#define N_EDGE   200000
#define EMBED    256
#define PAIR_DIM 128
#define HEADS    16
#define LN_EPS   1e-5f
#define SCALING  0.25f            // folded into Wq rows of Wall

// ---------------- scratch (device globals; no allocation) ----------------
__device__ uint4 g_qnh4 [N_NODE * 32];        // qn fp16 (256/row)
__device__ uint4 g_Wallh4[768 * 32];          // Wall fp16: Wq*S, Wk, Wvf, pad
__device__ uint4 g_qh4[N_NODE * 32];          // q fp16
__device__ uint4 g_kh4[N_NODE * 32];          // k fp16
__device__ uint4 g_vwh4[N_NODE * 6];          // vw fp16 [n][d*16+h] (96B/row)
__device__ float g_ex[N_EDGE * HEADS];
__device__ float g_denom[N_NODE * HEADS];     // after recip: 1/denom
__device__ float g_bias[N_EDGE * HEADS];      // FINAL per-head logit bias
__device__ uint4 g_Wbp4[16 * 16];             // Wb' fp16 [16 x 128]
__device__ float g_t1[HEADS];
__device__ float g_t2p[HEADS];                // t2 + bb

__device__ __forceinline__ unsigned smem_u32(const void* p) {
    unsigned a;
    asm("{ .reg .u64 t; cvta.to.shared.u64 t, %1; cvt.u32.u64 %0, t; }" : "=r"(a) : "l"(p));
    return a;
}

// ---------------- 1. fused prep (one launch; NO pair pass) ----------------
#define PB_WALL 768
#define PB_LN   2500
#define PB_INIT 1250
#define PB_WBP  8
#define PB_T    2
#define PREP_BLKS (PB_WALL + PB_LN + PB_INIT + PB_WBP + PB_T)
__global__ __launch_bounds__(256) void prep(
        const float* __restrict__ query,
        const float* __restrict__ ln_w, const float* __restrict__ ln_b,
        const float* __restrict__ Wq, const float* __restrict__ Wk,
        const float* __restrict__ Wv,
        const float* __restrict__ Wf1, const float* __restrict__ Wf2,
        const float* __restrict__ Wf3,
        float* __restrict__ out,
        const float* __restrict__ bf1, const float* __restrict__ bf2,
        const float* __restrict__ bf3,
        const float* __restrict__ pln_w, const float* __restrict__ pln_b,
        const float* __restrict__ Wb, const float* __restrict__ bb) {
    int blk = blockIdx.x;
    if (blk < PB_WALL) {
        int idx = blk * 256 + threadIdx.x;
        int row = idx >> 8;
        int c   = idx & 255;
        float val = 0.f;
        if (row < 256) {
            val = Wq[row * EMBED + c] * SCALING;
        } else if (row < 512) {
            val = Wk[(row - 256) * EMBED + c];
        } else if (row < 560) {
            int r = row - 512;
            int d = r >> 4, h = r & 15;
            const float* Wf = (d == 0) ? Wf1 : (d == 1) ? Wf2 : Wf3;
            float s = 0.f;
            #pragma unroll
            for (int hd = 0; hd < 16; hd++)
                s += Wf[h * 16 + hd] * Wv[(h * 16 + hd) * EMBED + c];
            val = s;
        }
        ((__half*)g_Wallh4)[idx] = __float2half_rn(val);
        return;
    }
    blk -= PB_WALL;
    if (blk < PB_LN) {
        int node = blk * 8 + (threadIdx.x >> 5);
        int lane = threadIdx.x & 31;
        if (node >= N_NODE) return;
        const float4* x = (const float4*)(query + (size_t)node * EMBED);
        float4 v[2];
        float s = 0.f, sq = 0.f;
        #pragma unroll
        for (int i = 0; i < 2; i++) {
            v[i] = x[lane + 32 * i];
            s  += v[i].x + v[i].y + v[i].z + v[i].w;
            sq += v[i].x*v[i].x + v[i].y*v[i].y + v[i].z*v[i].z + v[i].w*v[i].w;
        }
        #pragma unroll
        for (int o = 16; o > 0; o >>= 1) {
            s  += __shfl_xor_sync(0xffffffffu, s,  o);
            sq += __shfl_xor_sync(0xffffffffu, sq, o);
        }
        float mean = s * (1.f / EMBED);
        float var  = sq * (1.f / EMBED) - mean * mean;
        float rstd = rsqrtf(var + LN_EPS);
        uint2* o = (uint2*)g_qnh4 + (size_t)node * 64;
        #pragma unroll
        for (int i = 0; i < 2; i++) {
            int j = lane + 32 * i;
            float4 w = ((const float4*)ln_w)[j];
            float4 b = ((const float4*)ln_b)[j];
            float rx = (v[i].x - mean) * rstd * w.x + b.x;
            float ry = (v[i].y - mean) * rstd * w.y + b.y;
            float rz = (v[i].z - mean) * rstd * w.z + b.z;
            float rw = (v[i].w - mean) * rstd * w.w + b.w;
            uint2 pk;
            __half2 p0 = __floats2half2_rn(rx, ry);
            __half2 p1 = __floats2half2_rn(rz, rw);
            pk.x = *(unsigned*)&p0;
            pk.y = *(unsigned*)&p1;
            o[j] = pk;
        }
        return;
    }
    blk -= PB_LN;
    if (blk < PB_INIT) {
        int i = blk * 256 + threadIdx.x;
        if (i < N_NODE * HEADS) g_denom[i] = 0.f;
        if (i < N_NODE * 3) {
            int d = i % 3;
            out[i] = (d == 0) ? bf1[0] : (d == 1) ? bf2[0] : bf3[0];
        }
        return;
    }
    blk -= PB_INIT;
    if (blk < PB_WBP) {
        int idx = blk * 256 + threadIdx.x;       // 0..2047
        int h = idx >> 7, c = idx & 127;
        ((__half*)g_Wbp4)[idx] = __float2half_rn(pln_w[c] * Wb[h * PAIR_DIM + c]);
        return;
    }
    blk -= PB_WBP;
    {
        int h = blk * 8 + (threadIdx.x >> 5);
        int lane = threadIdx.x & 31;
        if (h >= HEADS) return;
        float t1 = 0.f, t2 = 0.f;
        #pragma unroll
        for (int i = 0; i < 4; i++) {
            int c = lane + 32 * i;
            float wb = Wb[h * PAIR_DIM + c];
            t1 += pln_w[c] * wb;
            t2 += pln_b[c] * wb;
        }
        #pragma unroll
        for (int o = 16; o > 0; o >>= 1) {
            t1 += __shfl_xor_sync(0xffffffffu, t1, o);
            t2 += __shfl_xor_sync(0xffffffffu, t2, o);
        }
        if (lane == 0) {
            g_t1[h]  = t1;
            g_t2p[h] = t2 + bb[h];
        }
    }
}

// ---------------- 2. HMMA GEMM: C[20000 x 640] = qn . Wall^T ----------------
#define APAD 72
__global__ __launch_bounds__(256) void gemm_mma() {
    __shared__ __half As[128][APAD];
    __shared__ __half Bs[128][APAD];
    int tid  = threadIdx.x;
    int wid  = tid >> 5;
    int lane = tid & 31;
    int wm = wid >> 1;
    int wn = wid & 1;
    int m0  = blockIdx.y * 128;
    int n0g = blockIdx.x * 128;

    float acc[2][8][4];
    #pragma unroll
    for (int i = 0; i < 2; i++)
        #pragma unroll
        for (int j = 0; j < 8; j++)
            #pragma unroll
            for (int t = 0; t < 4; t++) acc[i][j][t] = 0.f;

    const int fr = tid >> 3;
    const int fu = tid & 7;

    for (int k0 = 0; k0 < EMBED; k0 += 64) {
        #pragma unroll
        for (int i = 0; i < 4; i++) {
            int row = fr + 32 * i;
            int m = m0 + row;
            uint4 av = make_uint4(0, 0, 0, 0);
            if (m < N_NODE) av = g_qnh4[(size_t)m * 32 + (k0 >> 3) + fu];
            *(uint4*)&As[row][fu * 8] = av;
            uint4 bv = g_Wallh4[(size_t)(n0g + row) * 32 + (k0 >> 3) + fu];
            *(uint4*)&Bs[row][fu * 8] = bv;
        }
        __syncthreads();

        #pragma unroll
        for (int kk = 0; kk < 4; kk++) {
            int kc = kk * 16;
            unsigned a[2][4];
            #pragma unroll
            for (int mt = 0; mt < 2; mt++) {
                int row = wm * 32 + mt * 16 + (lane & 15);
                int col = kc + ((lane >> 4) << 3);
                unsigned addr = smem_u32(&As[row][col]);
                asm volatile("ldmatrix.sync.aligned.m8n8.x4.shared.b16 {%0,%1,%2,%3}, [%4];"
                             : "=r"(a[mt][0]), "=r"(a[mt][1]), "=r"(a[mt][2]), "=r"(a[mt][3])
                             : "r"(addr));
            }
            unsigned b[8][2];
            #pragma unroll
            for (int p = 0; p < 4; p++) {
                int row = wn * 64 + p * 16 + ((lane >> 4) << 3) + (lane & 7);
                int col = kc + (((lane >> 3) & 1) << 3);
                unsigned addr = smem_u32(&Bs[row][col]);
                asm volatile("ldmatrix.sync.aligned.m8n8.x4.shared.b16 {%0,%1,%2,%3}, [%4];"
                             : "=r"(b[2*p][0]), "=r"(b[2*p][1]), "=r"(b[2*p+1][0]), "=r"(b[2*p+1][1])
                             : "r"(addr));
            }
            #pragma unroll
            for (int mt = 0; mt < 2; mt++)
                #pragma unroll
                for (int nt = 0; nt < 8; nt++)
                    asm volatile("mma.sync.aligned.m16n8k16.row.col.f32.f16.f16.f32 "
                                 "{%0,%1,%2,%3}, {%4,%5,%6,%7}, {%8,%9}, {%0,%1,%2,%3};"
                                 : "+f"(acc[mt][nt][0]), "+f"(acc[mt][nt][1]),
                                   "+f"(acc[mt][nt][2]), "+f"(acc[mt][nt][3])
                                 : "r"(a[mt][0]), "r"(a[mt][1]), "r"(a[mt][2]), "r"(a[mt][3]),
                                   "r"(b[nt][0]), "r"(b[nt][1]));
        }
        __syncthreads();
    }

    int gr = lane >> 2, gc = lane & 3;
    __half* qh = (__half*)g_qh4;
    __half* kh = (__half*)g_kh4;
    __half* vwh = (__half*)g_vwh4;
    #pragma unroll
    for (int mt = 0; mt < 2; mt++) {
        #pragma unroll
        for (int hf = 0; hf < 2; hf++) {
            int m = m0 + wm * 32 + mt * 16 + gr + hf * 8;
            if (m >= N_NODE) continue;
            #pragma unroll
            for (int nt = 0; nt < 8; nt++) {
                float c0 = acc[mt][nt][hf * 2 + 0];
                float c1 = acc[mt][nt][hf * 2 + 1];
                int colg = n0g + wn * 64 + nt * 8 + gc * 2;
                if (colg < 256) {
                    __half2 h = __floats2half2_rn(c0, c1);
                    *(__half2*)&qh[(size_t)m * 256 + colg] = h;
                } else if (colg < 512) {
                    __half2 h = __floats2half2_rn(c0, c1);
                    *(__half2*)&kh[(size_t)m * 256 + (colg - 256)] = h;
                } else if (colg < 560) {
                    __half2 h = __floats2half2_rn(c0, c1);
                    *(__half2*)&vwh[(size_t)m * 48 + (colg - 512)] = h;
                }
            }
        }
    }
}

// ---------------- 3. bias GEMM: fp32 pair in, half-warp-row fill, LN-folded --
__global__ __launch_bounds__(128) void bias_gemm(const float* __restrict__ pair) {
    __shared__ __half As[128][136];
    __shared__ __half Bs[16][136];
    __shared__ float2 sStat[128];          // (rstd, mean*rstd)
    int tid  = threadIdx.x;
    int wid  = tid >> 5;
    int lane = tid & 31;
    int m0 = blockIdx.x * 128;

    int half = lane >> 4;      // 0/1: row within pair
    int hl   = lane & 15;      // position in half-warp
    #pragma unroll
    for (int i = 0; i < 16; i++) {
        int row = wid * 2 + 8 * i + half;       // tiles all 128 rows uniquely
        int e = m0 + row;
        float4 pa = make_float4(0.f, 0.f, 0.f, 0.f);
        float4 pb = pa;
        if (e < N_EDGE) {
            const float4* pr = (const float4*)(pair + (size_t)e * PAIR_DIM);
            pa = pr[hl * 2];
            pb = pr[hl * 2 + 1];
        }
        float s  = pa.x + pa.y + pa.z + pa.w + pb.x + pb.y + pb.z + pb.w;
        float sq = pa.x*pa.x + pa.y*pa.y + pa.z*pa.z + pa.w*pa.w
                 + pb.x*pb.x + pb.y*pb.y + pb.z*pb.z + pb.w*pb.w;
        #pragma unroll
        for (int o = 1; o < 16; o <<= 1) {       // segmented within half-warp
            s  += __shfl_xor_sync(0xffffffffu, s,  o);
            sq += __shfl_xor_sync(0xffffffffu, sq, o);
        }
        if (hl == 0) {
            float mean = s * (1.f / PAIR_DIM);
            float var  = sq * (1.f / PAIR_DIM) - mean * mean;
            float rstd = rsqrtf(var + LN_EPS);
            sStat[row] = make_float2(rstd, mean * rstd);
        }
        uint4 pk;
        __half2 h0 = __floats2half2_rn(pa.x, pa.y);
        __half2 h1 = __floats2half2_rn(pa.z, pa.w);
        __half2 h2 = __floats2half2_rn(pb.x, pb.y);
        __half2 h3 = __floats2half2_rn(pb.z, pb.w);
        pk.x = *(unsigned*)&h0;
        pk.y = *(unsigned*)&h1;
        pk.z = *(unsigned*)&h2;
        pk.w = *(unsigned*)&h3;
        *(uint4*)&As[row][hl * 8] = pk;
    }
    // fill B: 16 rows x 16 uint4
    #pragma unroll
    for (int i = 0; i < 2; i++) {
        int v = tid + 128 * i;
        int row = v >> 4, u = v & 15;
        *(uint4*)&Bs[row][u * 8] = g_Wbp4[row * 16 + u];
    }
    __syncthreads();

    float acc[2][2][4];
    #pragma unroll
    for (int i = 0; i < 2; i++)
        #pragma unroll
        for (int j = 0; j < 2; j++)
            #pragma unroll
            for (int t = 0; t < 4; t++) acc[i][j][t] = 0.f;

    #pragma unroll
    for (int kk = 0; kk < 8; kk++) {
        int kc = kk * 16;
        unsigned a[2][4];
        #pragma unroll
        for (int mt = 0; mt < 2; mt++) {
            int row = wid * 32 + mt * 16 + (lane & 15);
            int col = kc + ((lane >> 4) << 3);
            unsigned addr = smem_u32(&As[row][col]);
            asm volatile("ldmatrix.sync.aligned.m8n8.x4.shared.b16 {%0,%1,%2,%3}, [%4];"
                         : "=r"(a[mt][0]), "=r"(a[mt][1]), "=r"(a[mt][2]), "=r"(a[mt][3])
                         : "r"(addr));
        }
        unsigned b[2][2];
        {
            int row = ((lane >> 4) << 3) + (lane & 7);
            int col = kc + (((lane >> 3) & 1) << 3);
            unsigned addr = smem_u32(&Bs[row][col]);
            asm volatile("ldmatrix.sync.aligned.m8n8.x4.shared.b16 {%0,%1,%2,%3}, [%4];"
                         : "=r"(b[0][0]), "=r"(b[0][1]), "=r"(b[1][0]), "=r"(b[1][1])
                         : "r"(addr));
        }
        #pragma unroll
        for (int mt = 0; mt < 2; mt++)
            #pragma unroll
            for (int nt = 0; nt < 2; nt++)
                asm volatile("mma.sync.aligned.m16n8k16.row.col.f32.f16.f16.f32 "
                             "{%0,%1,%2,%3}, {%4,%5,%6,%7}, {%8,%9}, {%0,%1,%2,%3};"
                             : "+f"(acc[mt][nt][0]), "+f"(acc[mt][nt][1]),
                               "+f"(acc[mt][nt][2]), "+f"(acc[mt][nt][3])
                             : "r"(a[mt][0]), "r"(a[mt][1]), "r"(a[mt][2]), "r"(a[mt][3]),
                               "r"(b[nt][0]), "r"(b[nt][1]));
    }

    // epilogue: finalize bias = rstd*dot - mean*rstd*t1[h] + t2p[h]
    int gr = lane >> 2, gc = lane & 3;
    float t1v[4], t2v[4];
    #pragma unroll
    for (int nt = 0; nt < 2; nt++) {
        t1v[nt*2+0] = g_t1[nt*8 + gc*2 + 0];
        t1v[nt*2+1] = g_t1[nt*8 + gc*2 + 1];
        t2v[nt*2+0] = g_t2p[nt*8 + gc*2 + 0];
        t2v[nt*2+1] = g_t2p[nt*8 + gc*2 + 1];
    }
    #pragma unroll
    for (int mt = 0; mt < 2; mt++) {
        #pragma unroll
        for (int hf = 0; hf < 2; hf++) {
            int row = wid * 32 + mt * 16 + gr + hf * 8;
            int e = m0 + row;
            if (e >= N_EDGE) continue;
            float2 st = sStat[row];
            #pragma unroll
            for (int nt = 0; nt < 2; nt++) {
                float d0 = acc[mt][nt][hf * 2 + 0];
                float d1 = acc[mt][nt][hf * 2 + 1];
                float2 f2;
                f2.x = fmaf(st.x, d0, fmaf(-st.y, t1v[nt*2+0], t2v[nt*2+0]));
                f2.y = fmaf(st.x, d1, fmaf(-st.y, t1v[nt*2+1], t2v[nt*2+1]));
                *(float2*)&g_bias[(size_t)e * 16 + nt * 8 + gc * 2] = f2;
            }
        }
    }
}

// ---------------- 4. qk + exp + denom (2 edges/warp, dual half2 chains) -----
__global__ __launch_bounds__(256) void qk_exp(const int* __restrict__ ei) {
    int w = (blockIdx.x * blockDim.x + threadIdx.x) >> 5;   // warp id
    int lane = threadIdx.x & 31;
    int e0 = 2 * w;
    int e1 = 2 * w + 1;
    if (e0 >= N_EDGE) return;
    int src0 = ei[4 * w + 0], dst0 = ei[4 * w + 1];
    int src1 = ei[4 * w + 2], dst1 = ei[4 * w + 3];

    // 4 independent gathers issued back-to-back (MLP=4)
    uint4 q0 = g_qh4[(size_t)src0 * 32 + lane];
    uint4 k0 = g_kh4[(size_t)dst0 * 32 + lane];
    uint4 q1 = g_qh4[(size_t)src1 * 32 + lane];
    uint4 k1 = g_kh4[(size_t)dst1 * 32 + lane];

    const __half2* q0h = (const __half2*)&q0;
    const __half2* k0h = (const __half2*)&k0;
    const __half2* q1h = (const __half2*)&q1;
    const __half2* k1h = (const __half2*)&k1;
    // per edge: 2 independent half2 chains (depth 2), then combine
    __half2 a0 = __hmul2(q0h[0], k0h[0]);
    __half2 b0 = __hmul2(q0h[1], k0h[1]);
    __half2 a1 = __hmul2(q1h[0], k1h[0]);
    __half2 b1 = __hmul2(q1h[1], k1h[1]);
    a0 = __hfma2(q0h[2], k0h[2], a0);
    b0 = __hfma2(q0h[3], k0h[3], b0);
    a1 = __hfma2(q1h[2], k1h[2], a1);
    b1 = __hfma2(q1h[3], k1h[3], b1);
    a0 = __hadd2(a0, b0);
    a1 = __hadd2(a1, b1);
    float2 f0 = __half22float2(a0);
    float2 f1 = __half22float2(a1);
    float qk0 = f0.x + f0.y;
    float qk1 = f1.x + f1.y;
    qk0 += __shfl_xor_sync(0xffffffffu, qk0, 1);   // head h = lane>>1
    qk1 += __shfl_xor_sync(0xffffffffu, qk1, 1);

    int h = lane >> 1;
    if (!(lane & 1)) {
        float ex0 = __expf(qk0 + g_bias[(size_t)e0 * 16 + h]);
        float ex1 = __expf(qk1 + g_bias[(size_t)e1 * 16 + h]);
        g_ex[(size_t)e0 * HEADS + h] = ex0;
        g_ex[(size_t)e1 * HEADS + h] = ex1;
        atomicAdd(&g_denom[src0 * HEADS + h], ex0);
        atomicAdd(&g_denom[src1 * HEADS + h], ex1);
    }
}

// ---------------- 5. reciprocal of denom (in place) ----------------
__global__ void recip_denom() {
    int i = blockIdx.x * blockDim.x + threadIdx.x;
    if (i >= (N_NODE * HEADS) / 4) return;
    float4 d = ((const float4*)g_denom)[i];
    float4 r;
    r.x = __frcp_rn(d.x);
    r.y = __frcp_rn(d.y);
    r.z = __frcp_rn(d.z);
    r.w = __frcp_rn(d.w);
    ((float4*)g_denom)[i] = r;
}

// ---------------- 6. scatter output (thread per edge, fp16 vw) ----------------
__global__ void scatter_out(const int* __restrict__ ei, const float* __restrict__ edge_diff,
                            float* __restrict__ out) {
    int e = blockIdx.x * blockDim.x + threadIdx.x;
    if (e >= N_EDGE) return;
    int src = ei[2 * e];
    int dst = ei[2 * e + 1];

    const float4* exv = (const float4*)(g_ex + (size_t)e * HEADS);
    const float4* dnv = (const float4*)(g_denom + src * HEADS);   // reciprocals
    float prob[16];
    #pragma unroll
    for (int i = 0; i < 4; i++) {
        float4 ex4 = exv[i];
        float4 rd4 = dnv[i];
        prob[4*i+0] = ex4.x * rd4.x;
        prob[4*i+1] = ex4.y * rd4.y;
        prob[4*i+2] = ex4.z * rd4.z;
        prob[4*i+3] = ex4.w * rd4.w;
    }
    // vw fp16: 6 uint4 per node row; [d*16+h], 8 halves per uint4
    const uint4* vw4 = &g_vwh4[(size_t)dst * 6];
    uint4 v[6];
    #pragma unroll
    for (int i = 0; i < 6; i++) v[i] = vw4[i];
    float s[3] = {0.f, 0.f, 0.f};
    #pragma unroll
    for (int d = 0; d < 3; d++) {
        const __half2* hp = (const __half2*)&v[d * 2];
        #pragma unroll
        for (int j = 0; j < 8; j++) {
            float2 f = __half22float2(hp[j]);
            s[d] += prob[2*j] * f.x + prob[2*j+1] * f.y;
        }
    }
    const float* ed = edge_diff + (size_t)e * 3;
    atomicAdd(&out[src * 3 + 0], ed[0] * s[0]);
    atomicAdd(&out[src * 3 + 1], ed[1] * s[1]);
    atomicAdd(&out[src * 3 + 2], ed[2] * s[2]);
}

// ---------------- launch ----------------
extern "C" void kernel_launch(void* const* d_in, const int* in_sizes, int n_in,
                              void* d_out, int out_size) {
    const float* query      = (const float*)d_in[0];
    const int*   edge_index = (const int*)  d_in[1];
    const float* edge_diff  = (const float*)d_in[2];
    const float* pair       = (const float*)d_in[3];
    const float* ln_w       = (const float*)d_in[4];
    const float* ln_b       = (const float*)d_in[5];
    const float* pln_w      = (const float*)d_in[6];
    const float* pln_b      = (const float*)d_in[7];
    const float* Wq         = (const float*)d_in[8];
    const float* Wk         = (const float*)d_in[9];
    const float* Wv         = (const float*)d_in[10];
    const float* Wb         = (const float*)d_in[11];
    const float* bb         = (const float*)d_in[12];
    const float* Wf1        = (const float*)d_in[13];
    const float* bf1        = (const float*)d_in[14];
    const float* Wf2        = (const float*)d_in[15];
    const float* bf2        = (const float*)d_in[16];
    const float* Wf3        = (const float*)d_in[17];
    const float* bf3        = (const float*)d_in[18];
    float* out = (float*)d_out;

    prep<<<PREP_BLKS, 256>>>(query, ln_w, ln_b, Wq, Wk, Wv, Wf1, Wf2, Wf3,
                             out, bf1, bf2, bf3, pln_w, pln_b, Wb, bb);
    bias_gemm<<<(N_EDGE + 127) / 128, 128>>>(pair);
    gemm_mma<<<dim3(5, (N_NODE + 127) / 128), 256>>>();
    qk_exp<<<(N_EDGE / 2 * 32 + 255) / 256, 256>>>(edge_index);
    recip_denom<<<(N_NODE * HEADS / 4 + 255) / 256, 256>>>();
    scatter_out<<<(N_EDGE + 255) / 256, 256>>>(edge_index, edge_diff, out);
}

// round 16
// speedup vs baseline: 1.0792x; 1.0412x over previous
#include <cuda_runtime.h>
#include <cuda_fp16.h>
#include <cstdint>
#include <math.h>

#define N_NODE   20000
#define N_EDGE   200000
#define EMBED    256
#define PAIR_DIM 128
#define HEADS    16
#define LN_EPS   1e-5f
#define SCALING  0.25f            // folded into Wq rows of Wall

// ---------------- scratch (device globals; no allocation) ----------------
__device__ uint4 g_qnh4 [N_NODE * 32];        // qn fp16 (256/row)
__device__ uint4 g_Wallh4[768 * 32];          // Wall fp16: Wq*S, Wk, Wvf, pad
__device__ uint4 g_qh4[N_NODE * 32];          // q fp16
__device__ uint4 g_kh4[N_NODE * 32];          // k fp16
__device__ uint4 g_vwh4[N_NODE * 6];          // vw fp16 [n][d*16+h] (96B/row)
__device__ float g_ex[N_EDGE * HEADS];
__device__ float g_denom[N_NODE * HEADS];     // after recip: 1/denom
__device__ float g_bias[N_EDGE * HEADS];      // FINAL per-head logit bias
__device__ uint4 g_Wbp4[16 * 16];             // Wb' fp16 [16 x 128]
__device__ float g_t1[HEADS];
__device__ float g_t2p[HEADS];                // t2 + bb

__device__ __forceinline__ unsigned smem_u32(const void* p) {
    unsigned a;
    asm("{ .reg .u64 t; cvta.to.shared.u64 t, %1; cvt.u32.u64 %0, t; }" : "=r"(a) : "l"(p));
    return a;
}

// ---------------- 1. fused prep (one launch; NO pair pass) ----------------
#define PB_WALL 768
#define PB_LN   2500
#define PB_INIT 1250
#define PB_WBP  8
#define PB_T    2
#define PREP_BLKS (PB_WALL + PB_LN + PB_INIT + PB_WBP + PB_T)
__global__ __launch_bounds__(256) void prep(
        const float* __restrict__ query,
        const float* __restrict__ ln_w, const float* __restrict__ ln_b,
        const float* __restrict__ Wq, const float* __restrict__ Wk,
        const float* __restrict__ Wv,
        const float* __restrict__ Wf1, const float* __restrict__ Wf2,
        const float* __restrict__ Wf3,
        float* __restrict__ out,
        const float* __restrict__ bf1, const float* __restrict__ bf2,
        const float* __restrict__ bf3,
        const float* __restrict__ pln_w, const float* __restrict__ pln_b,
        const float* __restrict__ Wb, const float* __restrict__ bb) {
    int blk = blockIdx.x;
    if (blk < PB_WALL) {
        int idx = blk * 256 + threadIdx.x;
        int row = idx >> 8;
        int c   = idx & 255;
        float val = 0.f;
        if (row < 256) {
            val = Wq[row * EMBED + c] * SCALING;
        } else if (row < 512) {
            val = Wk[(row - 256) * EMBED + c];
        } else if (row < 560) {
            int r = row - 512;
            int d = r >> 4, h = r & 15;
            const float* Wf = (d == 0) ? Wf1 : (d == 1) ? Wf2 : Wf3;
            float s = 0.f;
            #pragma unroll
            for (int hd = 0; hd < 16; hd++)
                s += Wf[h * 16 + hd] * Wv[(h * 16 + hd) * EMBED + c];
            val = s;
        }
        ((__half*)g_Wallh4)[idx] = __float2half_rn(val);
        return;
    }
    blk -= PB_WALL;
    if (blk < PB_LN) {
        int node = blk * 8 + (threadIdx.x >> 5);
        int lane = threadIdx.x & 31;
        if (node >= N_NODE) return;
        const float4* x = (const float4*)(query + (size_t)node * EMBED);
        float4 v[2];
        float s = 0.f, sq = 0.f;
        #pragma unroll
        for (int i = 0; i < 2; i++) {
            v[i] = x[lane + 32 * i];
            s  += v[i].x + v[i].y + v[i].z + v[i].w;
            sq += v[i].x*v[i].x + v[i].y*v[i].y + v[i].z*v[i].z + v[i].w*v[i].w;
        }
        #pragma unroll
        for (int o = 16; o > 0; o >>= 1) {
            s  += __shfl_xor_sync(0xffffffffu, s,  o);
            sq += __shfl_xor_sync(0xffffffffu, sq, o);
        }
        float mean = s * (1.f / EMBED);
        float var  = sq * (1.f / EMBED) - mean * mean;
        float rstd = rsqrtf(var + LN_EPS);
        uint2* o = (uint2*)g_qnh4 + (size_t)node * 64;
        #pragma unroll
        for (int i = 0; i < 2; i++) {
            int j = lane + 32 * i;
            float4 w = ((const float4*)ln_w)[j];
            float4 b = ((const float4*)ln_b)[j];
            float rx = (v[i].x - mean) * rstd * w.x + b.x;
            float ry = (v[i].y - mean) * rstd * w.y + b.y;
            float rz = (v[i].z - mean) * rstd * w.z + b.z;
            float rw = (v[i].w - mean) * rstd * w.w + b.w;
            uint2 pk;
            __half2 p0 = __floats2half2_rn(rx, ry);
            __half2 p1 = __floats2half2_rn(rz, rw);
            pk.x = *(unsigned*)&p0;
            pk.y = *(unsigned*)&p1;
            o[j] = pk;
        }
        return;
    }
    blk -= PB_LN;
    if (blk < PB_INIT) {
        int i = blk * 256 + threadIdx.x;
        if (i < N_NODE * HEADS) g_denom[i] = 0.f;
        if (i < N_NODE * 3) {
            int d = i % 3;
            out[i] = (d == 0) ? bf1[0] : (d == 1) ? bf2[0] : bf3[0];
        }
        return;
    }
    blk -= PB_INIT;
    if (blk < PB_WBP) {
        int idx = blk * 256 + threadIdx.x;       // 0..2047
        int h = idx >> 7, c = idx & 127;
        ((__half*)g_Wbp4)[idx] = __float2half_rn(pln_w[c] * Wb[h * PAIR_DIM + c]);
        return;
    }
    blk -= PB_WBP;
    {
        int h = blk * 8 + (threadIdx.x >> 5);
        int lane = threadIdx.x & 31;
        if (h >= HEADS) return;
        float t1 = 0.f, t2 = 0.f;
        #pragma unroll
        for (int i = 0; i < 4; i++) {
            int c = lane + 32 * i;
            float wb = Wb[h * PAIR_DIM + c];
            t1 += pln_w[c] * wb;
            t2 += pln_b[c] * wb;
        }
        #pragma unroll
        for (int o = 16; o > 0; o >>= 1) {
            t1 += __shfl_xor_sync(0xffffffffu, t1, o);
            t2 += __shfl_xor_sync(0xffffffffu, t2, o);
        }
        if (lane == 0) {
            g_t1[h]  = t1;
            g_t2p[h] = t2 + bb[h];
        }
    }
}

// ---------------- 2. HMMA GEMM: C[20000 x 640] = qn . Wall^T ----------------
#define APAD 72
__global__ __launch_bounds__(256) void gemm_mma() {
    __shared__ __half As[128][APAD];
    __shared__ __half Bs[128][APAD];
    int tid  = threadIdx.x;
    int wid  = tid >> 5;
    int lane = tid & 31;
    int wm = wid >> 1;
    int wn = wid & 1;
    int m0  = blockIdx.y * 128;
    int n0g = blockIdx.x * 128;

    float acc[2][8][4];
    #pragma unroll
    for (int i = 0; i < 2; i++)
        #pragma unroll
        for (int j = 0; j < 8; j++)
            #pragma unroll
            for (int t = 0; t < 4; t++) acc[i][j][t] = 0.f;

    const int fr = tid >> 3;
    const int fu = tid & 7;

    for (int k0 = 0; k0 < EMBED; k0 += 64) {
        #pragma unroll
        for (int i = 0; i < 4; i++) {
            int row = fr + 32 * i;
            int m = m0 + row;
            uint4 av = make_uint4(0, 0, 0, 0);
            if (m < N_NODE) av = g_qnh4[(size_t)m * 32 + (k0 >> 3) + fu];
            *(uint4*)&As[row][fu * 8] = av;
            uint4 bv = g_Wallh4[(size_t)(n0g + row) * 32 + (k0 >> 3) + fu];
            *(uint4*)&Bs[row][fu * 8] = bv;
        }
        __syncthreads();

        #pragma unroll
        for (int kk = 0; kk < 4; kk++) {
            int kc = kk * 16;
            unsigned a[2][4];
            #pragma unroll
            for (int mt = 0; mt < 2; mt++) {
                int row = wm * 32 + mt * 16 + (lane & 15);
                int col = kc + ((lane >> 4) << 3);
                unsigned addr = smem_u32(&As[row][col]);
                asm volatile("ldmatrix.sync.aligned.m8n8.x4.shared.b16 {%0,%1,%2,%3}, [%4];"
                             : "=r"(a[mt][0]), "=r"(a[mt][1]), "=r"(a[mt][2]), "=r"(a[mt][3])
                             : "r"(addr));
            }
            unsigned b[8][2];
            #pragma unroll
            for (int p = 0; p < 4; p++) {
                int row = wn * 64 + p * 16 + ((lane >> 4) << 3) + (lane & 7);
                int col = kc + (((lane >> 3) & 1) << 3);
                unsigned addr = smem_u32(&Bs[row][col]);
                asm volatile("ldmatrix.sync.aligned.m8n8.x4.shared.b16 {%0,%1,%2,%3}, [%4];"
                             : "=r"(b[2*p][0]), "=r"(b[2*p][1]), "=r"(b[2*p+1][0]), "=r"(b[2*p+1][1])
                             : "r"(addr));
            }
            #pragma unroll
            for (int mt = 0; mt < 2; mt++)
                #pragma unroll
                for (int nt = 0; nt < 8; nt++)
                    asm volatile("mma.sync.aligned.m16n8k16.row.col.f32.f16.f16.f32 "
                                 "{%0,%1,%2,%3}, {%4,%5,%6,%7}, {%8,%9}, {%0,%1,%2,%3};"
                                 : "+f"(acc[mt][nt][0]), "+f"(acc[mt][nt][1]),
                                   "+f"(acc[mt][nt][2]), "+f"(acc[mt][nt][3])
                                 : "r"(a[mt][0]), "r"(a[mt][1]), "r"(a[mt][2]), "r"(a[mt][3]),
                                   "r"(b[nt][0]), "r"(b[nt][1]));
        }
        __syncthreads();
    }

    int gr = lane >> 2, gc = lane & 3;
    __half* qh = (__half*)g_qh4;
    __half* kh = (__half*)g_kh4;
    __half* vwh = (__half*)g_vwh4;
    #pragma unroll
    for (int mt = 0; mt < 2; mt++) {
        #pragma unroll
        for (int hf = 0; hf < 2; hf++) {
            int m = m0 + wm * 32 + mt * 16 + gr + hf * 8;
            if (m >= N_NODE) continue;
            #pragma unroll
            for (int nt = 0; nt < 8; nt++) {
                float c0 = acc[mt][nt][hf * 2 + 0];
                float c1 = acc[mt][nt][hf * 2 + 1];
                int colg = n0g + wn * 64 + nt * 8 + gc * 2;
                if (colg < 256) {
                    __half2 h = __floats2half2_rn(c0, c1);
                    *(__half2*)&qh[(size_t)m * 256 + colg] = h;
                } else if (colg < 512) {
                    __half2 h = __floats2half2_rn(c0, c1);
                    *(__half2*)&kh[(size_t)m * 256 + (colg - 256)] = h;
                } else if (colg < 560) {
                    __half2 h = __floats2half2_rn(c0, c1);
                    *(__half2*)&vwh[(size_t)m * 48 + (colg - 512)] = h;
                }
            }
        }
    }
}

// ---------------- 3. bias GEMM: fp32 pair in, half-warp-row fill, LN-folded --
__global__ __launch_bounds__(128) void bias_gemm(const float* __restrict__ pair) {
    __shared__ __half As[128][136];
    __shared__ __half Bs[16][136];
    __shared__ float2 sStat[128];          // (rstd, mean*rstd)
    int tid  = threadIdx.x;
    int wid  = tid >> 5;
    int lane = tid & 31;
    int m0 = blockIdx.x * 128;

    int half = lane >> 4;      // 0/1: row within pair
    int hl   = lane & 15;      // position in half-warp
    #pragma unroll
    for (int i = 0; i < 16; i++) {
        int row = wid * 2 + 8 * i + half;       // tiles all 128 rows uniquely
        int e = m0 + row;
        float4 pa = make_float4(0.f, 0.f, 0.f, 0.f);
        float4 pb = pa;
        if (e < N_EDGE) {
            const float4* pr = (const float4*)(pair + (size_t)e * PAIR_DIM);
            pa = pr[hl * 2];
            pb = pr[hl * 2 + 1];
        }
        float s  = pa.x + pa.y + pa.z + pa.w + pb.x + pb.y + pb.z + pb.w;
        float sq = pa.x*pa.x + pa.y*pa.y + pa.z*pa.z + pa.w*pa.w
                 + pb.x*pb.x + pb.y*pb.y + pb.z*pb.z + pb.w*pb.w;
        #pragma unroll
        for (int o = 1; o < 16; o <<= 1) {       // segmented within half-warp
            s  += __shfl_xor_sync(0xffffffffu, s,  o);
            sq += __shfl_xor_sync(0xffffffffu, sq, o);
        }
        if (hl == 0) {
            float mean = s * (1.f / PAIR_DIM);
            float var  = sq * (1.f / PAIR_DIM) - mean * mean;
            float rstd = rsqrtf(var + LN_EPS);
            sStat[row] = make_float2(rstd, mean * rstd);
        }
        uint4 pk;
        __half2 h0 = __floats2half2_rn(pa.x, pa.y);
        __half2 h1 = __floats2half2_rn(pa.z, pa.w);
        __half2 h2 = __floats2half2_rn(pb.x, pb.y);
        __half2 h3 = __floats2half2_rn(pb.z, pb.w);
        pk.x = *(unsigned*)&h0;
        pk.y = *(unsigned*)&h1;
        pk.z = *(unsigned*)&h2;
        pk.w = *(unsigned*)&h3;
        *(uint4*)&As[row][hl * 8] = pk;
    }
    // fill B: 16 rows x 16 uint4
    #pragma unroll
    for (int i = 0; i < 2; i++) {
        int v = tid + 128 * i;
        int row = v >> 4, u = v & 15;
        *(uint4*)&Bs[row][u * 8] = g_Wbp4[row * 16 + u];
    }
    __syncthreads();

    float acc[2][2][4];
    #pragma unroll
    for (int i = 0; i < 2; i++)
        #pragma unroll
        for (int j = 0; j < 2; j++)
            #pragma unroll
            for (int t = 0; t < 4; t++) acc[i][j][t] = 0.f;

    #pragma unroll
    for (int kk = 0; kk < 8; kk++) {
        int kc = kk * 16;
        unsigned a[2][4];
        #pragma unroll
        for (int mt = 0; mt < 2; mt++) {
            int row = wid * 32 + mt * 16 + (lane & 15);
            int col = kc + ((lane >> 4) << 3);
            unsigned addr = smem_u32(&As[row][col]);
            asm volatile("ldmatrix.sync.aligned.m8n8.x4.shared.b16 {%0,%1,%2,%3}, [%4];"
                         : "=r"(a[mt][0]), "=r"(a[mt][1]), "=r"(a[mt][2]), "=r"(a[mt][3])
                         : "r"(addr));
        }
        unsigned b[2][2];
        {
            int row = ((lane >> 4) << 3) + (lane & 7);
            int col = kc + (((lane >> 3) & 1) << 3);
            unsigned addr = smem_u32(&Bs[row][col]);
            asm volatile("ldmatrix.sync.aligned.m8n8.x4.shared.b16 {%0,%1,%2,%3}, [%4];"
                         : "=r"(b[0][0]), "=r"(b[0][1]), "=r"(b[1][0]), "=r"(b[1][1])
                         : "r"(addr));
        }
        #pragma unroll
        for (int mt = 0; mt < 2; mt++)
            #pragma unroll
            for (int nt = 0; nt < 2; nt++)
                asm volatile("mma.sync.aligned.m16n8k16.row.col.f32.f16.f16.f32 "
                             "{%0,%1,%2,%3}, {%4,%5,%6,%7}, {%8,%9}, {%0,%1,%2,%3};"
                             : "+f"(acc[mt][nt][0]), "+f"(acc[mt][nt][1]),
                               "+f"(acc[mt][nt][2]), "+f"(acc[mt][nt][3])
                             : "r"(a[mt][0]), "r"(a[mt][1]), "r"(a[mt][2]), "r"(a[mt][3]),
                               "r"(b[nt][0]), "r"(b[nt][1]));
    }

    // epilogue: finalize bias = rstd*dot - mean*rstd*t1[h] + t2p[h]
    int gr = lane >> 2, gc = lane & 3;
    float t1v[4], t2v[4];
    #pragma unroll
    for (int nt = 0; nt < 2; nt++) {
        t1v[nt*2+0] = g_t1[nt*8 + gc*2 + 0];
        t1v[nt*2+1] = g_t1[nt*8 + gc*2 + 1];
        t2v[nt*2+0] = g_t2p[nt*8 + gc*2 + 0];
        t2v[nt*2+1] = g_t2p[nt*8 + gc*2 + 1];
    }
    #pragma unroll
    for (int mt = 0; mt < 2; mt++) {
        #pragma unroll
        for (int hf = 0; hf < 2; hf++) {
            int row = wid * 32 + mt * 16 + gr + hf * 8;
            int e = m0 + row;
            if (e >= N_EDGE) continue;
            float2 st = sStat[row];
            #pragma unroll
            for (int nt = 0; nt < 2; nt++) {
                float d0 = acc[mt][nt][hf * 2 + 0];
                float d1 = acc[mt][nt][hf * 2 + 1];
                float2 f2;
                f2.x = fmaf(st.x, d0, fmaf(-st.y, t1v[nt*2+0], t2v[nt*2+0]));
                f2.y = fmaf(st.x, d1, fmaf(-st.y, t1v[nt*2+1], t2v[nt*2+1]));
                *(float2*)&g_bias[(size_t)e * 16 + nt * 8 + gc * 2] = f2;
            }
        }
    }
}

// ---------------- 4. qk + exp + denom (2 edges/warp, dual half2 chains) -----
__global__ __launch_bounds__(256) void qk_exp(const int* __restrict__ ei) {
    int w = (blockIdx.x * blockDim.x + threadIdx.x) >> 5;   // warp id
    int lane = threadIdx.x & 31;
    int e0 = 2 * w;
    int e1 = 2 * w + 1;
    if (e0 >= N_EDGE) return;
    int src0 = ei[4 * w + 0], dst0 = ei[4 * w + 1];
    int src1 = ei[4 * w + 2], dst1 = ei[4 * w + 3];

    // 4 independent gathers issued back-to-back (MLP=4)
    uint4 q0 = g_qh4[(size_t)src0 * 32 + lane];
    uint4 k0 = g_kh4[(size_t)dst0 * 32 + lane];
    uint4 q1 = g_qh4[(size_t)src1 * 32 + lane];
    uint4 k1 = g_kh4[(size_t)dst1 * 32 + lane];

    const __half2* q0h = (const __half2*)&q0;
    const __half2* k0h = (const __half2*)&k0;
    const __half2* q1h = (const __half2*)&q1;
    const __half2* k1h = (const __half2*)&k1;
    // per edge: 2 independent half2 chains (depth 2), then combine
    __half2 a0 = __hmul2(q0h[0], k0h[0]);
    __half2 b0 = __hmul2(q0h[1], k0h[1]);
    __half2 a1 = __hmul2(q1h[0], k1h[0]);
    __half2 b1 = __hmul2(q1h[1], k1h[1]);
    a0 = __hfma2(q0h[2], k0h[2], a0);
    b0 = __hfma2(q0h[3], k0h[3], b0);
    a1 = __hfma2(q1h[2], k1h[2], a1);
    b1 = __hfma2(q1h[3], k1h[3], b1);
    a0 = __hadd2(a0, b0);
    a1 = __hadd2(a1, b1);
    float2 f0 = __half22float2(a0);
    float2 f1 = __half22float2(a1);
    float qk0 = f0.x + f0.y;
    float qk1 = f1.x + f1.y;
    qk0 += __shfl_xor_sync(0xffffffffu, qk0, 1);   // head h = lane>>1
    qk1 += __shfl_xor_sync(0xffffffffu, qk1, 1);

    int h = lane >> 1;
    if (!(lane & 1)) {
        float ex0 = __expf(qk0 + g_bias[(size_t)e0 * 16 + h]);
        float ex1 = __expf(qk1 + g_bias[(size_t)e1 * 16 + h]);
        g_ex[(size_t)e0 * HEADS + h] = ex0;
        g_ex[(size_t)e1 * HEADS + h] = ex1;
        atomicAdd(&g_denom[src0 * HEADS + h], ex0);
        atomicAdd(&g_denom[src1 * HEADS + h], ex1);
    }
}

// ---------------- 5. reciprocal of denom (in place) ----------------
__global__ void recip_denom() {
    int i = blockIdx.x * blockDim.x + threadIdx.x;
    if (i >= (N_NODE * HEADS) / 4) return;
    float4 d = ((const float4*)g_denom)[i];
    float4 r;
    r.x = __frcp_rn(d.x);
    r.y = __frcp_rn(d.y);
    r.z = __frcp_rn(d.z);
    r.w = __frcp_rn(d.w);
    ((float4*)g_denom)[i] = r;
}

// ---------------- 6. scatter output (thread per edge, fp16 vw) ----------------
__global__ void scatter_out(const int* __restrict__ ei, const float* __restrict__ edge_diff,
                            float* __restrict__ out) {
    int e = blockIdx.x * blockDim.x + threadIdx.x;
    if (e >= N_EDGE) return;
    int src = ei[2 * e];
    int dst = ei[2 * e + 1];

    const float4* exv = (const float4*)(g_ex + (size_t)e * HEADS);
    const float4* dnv = (const float4*)(g_denom + src * HEADS);   // reciprocals
    float prob[16];
    #pragma unroll
    for (int i = 0; i < 4; i++) {
        float4 ex4 = exv[i];
        float4 rd4 = dnv[i];
        prob[4*i+0] = ex4.x * rd4.x;
        prob[4*i+1] = ex4.y * rd4.y;
        prob[4*i+2] = ex4.z * rd4.z;
        prob[4*i+3] = ex4.w * rd4.w;
    }
    // vw fp16: 6 uint4 per node row; [d*16+h], 8 halves per uint4
    const uint4* vw4 = &g_vwh4[(size_t)dst * 6];
    uint4 v[6];
    #pragma unroll
    for (int i = 0; i < 6; i++) v[i] = vw4[i];
    float s[3] = {0.f, 0.f, 0.f};
    #pragma unroll
    for (int d = 0; d < 3; d++) {
        const __half2* hp = (const __half2*)&v[d * 2];
        #pragma unroll
        for (int j = 0; j < 8; j++) {
            float2 f = __half22float2(hp[j]);
            s[d] += prob[2*j] * f.x + prob[2*j+1] * f.y;
        }
    }
    const float* ed = edge_diff + (size_t)e * 3;
    atomicAdd(&out[src * 3 + 0], ed[0] * s[0]);
    atomicAdd(&out[src * 3 + 1], ed[1] * s[1]);
    atomicAdd(&out[src * 3 + 2], ed[2] * s[2]);
}

// ---------------- launch (fork/join: bias_gemm overlaps gemm_mma) ----------
extern "C" void kernel_launch(void* const* d_in, const int* in_sizes, int n_in,
                              void* d_out, int out_size) {
    const float* query      = (const float*)d_in[0];
    const int*   edge_index = (const int*)  d_in[1];
    const float* edge_diff  = (const float*)d_in[2];
    const float* pair       = (const float*)d_in[3];
    const float* ln_w       = (const float*)d_in[4];
    const float* ln_b       = (const float*)d_in[5];
    const float* pln_w      = (const float*)d_in[6];
    const float* pln_b      = (const float*)d_in[7];
    const float* Wq         = (const float*)d_in[8];
    const float* Wk         = (const float*)d_in[9];
    const float* Wv         = (const float*)d_in[10];
    const float* Wb         = (const float*)d_in[11];
    const float* bb         = (const float*)d_in[12];
    const float* Wf1        = (const float*)d_in[13];
    const float* bf1        = (const float*)d_in[14];
    const float* Wf2        = (const float*)d_in[15];
    const float* bf2        = (const float*)d_in[16];
    const float* Wf3        = (const float*)d_in[17];
    const float* bf3        = (const float*)d_in[18];
    float* out = (float*)d_out;

    // created once, on the first (correctness) call — before graph capture.
    static cudaStream_t s2 = nullptr;
    static cudaEvent_t evFork = nullptr;
    static cudaEvent_t evJoin = nullptr;
    if (s2 == nullptr) {
        cudaStreamCreateWithFlags(&s2, cudaStreamNonBlocking);
        cudaEventCreateWithFlags(&evFork, cudaEventDisableTiming);
        cudaEventCreateWithFlags(&evJoin, cudaEventDisableTiming);
    }

    prep<<<PREP_BLKS, 256>>>(query, ln_w, ln_b, Wq, Wk, Wv, Wf1, Wf2, Wf3,
                             out, bf1, bf2, bf3, pln_w, pln_b, Wb, bb);

    // fork: bias_gemm on s2, gemm_mma on the main stream (independent)
    cudaEventRecord(evFork, 0);
    cudaStreamWaitEvent(s2, evFork, 0);
    bias_gemm<<<(N_EDGE + 127) / 128, 128, 0, s2>>>(pair);
    gemm_mma<<<dim3(5, (N_NODE + 127) / 128), 256>>>();
    // join before qk_exp (needs q/k from gemm_mma AND g_bias from bias_gemm)
    cudaEventRecord(evJoin, s2);
    cudaStreamWaitEvent(0, evJoin, 0);

    qk_exp<<<(N_EDGE / 2 * 32 + 255) / 256, 256>>>(edge_index);
    recip_denom<<<(N_NODE * HEADS / 4 + 255) / 256, 256>>>();
    scatter_out<<<(N_EDGE + 255) / 256, 256>>>(edge_index, edge_diff, out);
}